// round 15
// baseline (speedup 1.0000x reference)
#include <cuda_runtime.h>
#include <cuda_fp16.h>
#include <cstdint>

// Problem constants
#define T_LEN 1024
#define B_SZ  64
#define D_SZ  512
#define H_SZ  512
#define BH    (B_SZ * H_SZ)          // 32768
#define TBH   (T_LEN * BH)           // 33554432

// ---------------------------------------------------------------------------
// Scratch (static device globals; allocation-free per harness rules)
// ---------------------------------------------------------------------------
__device__ float  g_bc[D_SZ];
__device__ __half g_Wch[D_SZ * D_SZ];    // fused fc->layer0 weight, fp16
__device__ __half g_w1h[D_SZ * D_SZ];    // w1, fp16
__device__ __half g_xh[TBH];             // fp16(x)
__device__ __half g_o0h[TBH];            // fp16(out0)
__device__ __half g_pre[TBH];            // fp16 pre-activations (both layers)

// ---------------------------------------------------------------------------
// sm_80-compatible PTX helpers (cp.async / ldmatrix / mma.sync — base sm_103)
// ---------------------------------------------------------------------------
__device__ __forceinline__ uint32_t smem_u32(const void* p) {
    uint32_t a;
    asm("{ .reg .u64 t; cvta.to.shared.u64 t, %1; cvt.u32.u64 %0, t; }"
        : "=r"(a) : "l"(p));
    return a;
}

__device__ __forceinline__ void cp_async16(uint32_t dst, const void* src) {
    asm volatile("cp.async.cg.shared.global [%0], [%1], 16;"
                 :: "r"(dst), "l"(src));
}
__device__ __forceinline__ void cp_commit() {
    asm volatile("cp.async.commit_group;");
}
__device__ __forceinline__ void cp_wait1() {
    asm volatile("cp.async.wait_group 1;");
}
__device__ __forceinline__ void cp_wait6() {
    asm volatile("cp.async.wait_group 6;");
}
__device__ __forceinline__ void cp_wait0() {
    asm volatile("cp.async.wait_group 0;");
}

__device__ __forceinline__ void ldsm_x4(uint32_t& r0, uint32_t& r1,
                                        uint32_t& r2, uint32_t& r3,
                                        uint32_t addr) {
    asm volatile("ldmatrix.sync.aligned.m8n8.x4.shared.b16 {%0,%1,%2,%3}, [%4];"
                 : "=r"(r0), "=r"(r1), "=r"(r2), "=r"(r3) : "r"(addr));
}

__device__ __forceinline__ void mma_f16(float* d, const uint32_t* a,
                                        const uint32_t* b) {
    asm volatile(
        "mma.sync.aligned.m16n8k16.row.col.f32.f16.f16.f32 "
        "{%0,%1,%2,%3}, {%4,%5,%6,%7}, {%8,%9}, {%0,%1,%2,%3};"
        : "+f"(d[0]), "+f"(d[1]), "+f"(d[2]), "+f"(d[3])
        : "r"(a[0]), "r"(a[1]), "r"(a[2]), "r"(a[3]), "r"(b[0]), "r"(b[1]));
}

// ---------------------------------------------------------------------------
// Kernel 1: mega-prep. One launch, grid-partitioned (256 threads each):
//   blocks [0,64):      Wch = fp16(w0 @ fc_w)   (64x64 tiles, compute-bound)
//   blocks [64,320):    w1 -> fp16              (DRAM-bound)
//   blocks [320,322):   bc[h] = w0[h,:]·fc_b + b0[h]
//   blocks [322,33090): x -> fp16               (DRAM-bound, overlaps fuse)
// ---------------------------------------------------------------------------
#define PREP_FUSE_BLKS   64
#define PREP_W1_BLKS     256
#define PREP_BIAS_BLKS   2
#define PREP_X_BLKS      (TBH / 4 / 256)          // 32768
#define PREP_GRID        (PREP_FUSE_BLKS + PREP_W1_BLKS + PREP_BIAS_BLKS + PREP_X_BLKS)

__global__ __launch_bounds__(256)
void prep_kernel(const float* __restrict__ w0,
                 const float* __restrict__ fc_w,
                 const float* __restrict__ w1,
                 const float* __restrict__ fc_b,
                 const float* __restrict__ b0,
                 const float* __restrict__ x) {
    const int bid = blockIdx.x;
    const int tid = threadIdx.x;

    if (bid < PREP_FUSE_BLKS) {
        // ---- weight fusion GEMM: 64x64 tile ----
        __shared__ float As[16][64];   // As[k][m]
        __shared__ float Bs[16][64];   // Bs[k][n]
        const int ty = tid >> 4, tx = tid & 15;
        const int hBase = (bid >> 3) * 64;
        const int eBase = (bid & 7) * 64;

        float acc[4][4];
#pragma unroll
        for (int i = 0; i < 4; i++)
#pragma unroll
            for (int j = 0; j < 4; j++) acc[i][j] = 0.f;

        for (int k0 = 0; k0 < D_SZ; k0 += 16) {
            {
                int id = tid * 4;
                int row = id >> 4, col = id & 15;
                float4 v = *(const float4*)(w0 + (hBase + row) * D_SZ + k0 + col);
                As[col + 0][row] = v.x;
                As[col + 1][row] = v.y;
                As[col + 2][row] = v.z;
                As[col + 3][row] = v.w;
            }
            {
                int id = tid * 4;
                int r = id >> 6, c = id & 63;
                float4 v = *(const float4*)(fc_w + (k0 + r) * D_SZ + eBase + c);
                Bs[r][c + 0] = v.x;
                Bs[r][c + 1] = v.y;
                Bs[r][c + 2] = v.z;
                Bs[r][c + 3] = v.w;
            }
            __syncthreads();
#pragma unroll
            for (int k = 0; k < 16; k++) {
                float ra[4], rb[4];
#pragma unroll
                for (int i = 0; i < 4; i++) ra[i] = As[k][ty * 4 + i];
#pragma unroll
                for (int j = 0; j < 4; j++) rb[j] = Bs[k][tx * 4 + j];
#pragma unroll
                for (int i = 0; i < 4; i++)
#pragma unroll
                    for (int j = 0; j < 4; j++)
                        acc[i][j] = fmaf(ra[i], rb[j], acc[i][j]);
            }
            __syncthreads();
        }
#pragma unroll
        for (int i = 0; i < 4; i++)
#pragma unroll
            for (int j = 0; j < 4; j++)
                g_Wch[(hBase + ty * 4 + i) * D_SZ + eBase + tx * 4 + j] =
                    __float2half_rn(acc[i][j]);
    } else if (bid < PREP_FUSE_BLKS + PREP_W1_BLKS) {
        // ---- w1 fp32 -> fp16 ----
        int i = (bid - PREP_FUSE_BLKS) * 256 + tid;      // n4 = 65536
        float4 v = ((const float4*)w1)[i];
        __half2 a; a.x = __float2half_rn(v.x); a.y = __float2half_rn(v.y);
        __half2 b; b.x = __float2half_rn(v.z); b.y = __float2half_rn(v.w);
        ((__half2*)g_w1h)[i * 2 + 0] = a;
        ((__half2*)g_w1h)[i * 2 + 1] = b;
    } else if (bid < PREP_FUSE_BLKS + PREP_W1_BLKS + PREP_BIAS_BLKS) {
        // ---- fused bias ----
        int h = (bid - PREP_FUSE_BLKS - PREP_W1_BLKS) * 256 + tid;
        float acc = b0[h];
        const float* row = w0 + h * D_SZ;
#pragma unroll 8
        for (int d = 0; d < D_SZ; d++)
            acc = fmaf(row[d], fc_b[d], acc);
        g_bc[h] = acc;
    } else {
        // ---- x fp32 -> fp16 ----
        int i = (bid - PREP_FUSE_BLKS - PREP_W1_BLKS - PREP_BIAS_BLKS) * 256 + tid;
        float4 v = ((const float4*)x)[i];
        __half2 a; a.x = __float2half_rn(v.x); a.y = __float2half_rn(v.y);
        __half2 b; b.x = __float2half_rn(v.z); b.y = __float2half_rn(v.w);
        ((__half2*)g_xh)[i * 2 + 0] = a;
        ((__half2*)g_xh)[i * 2 + 1] = b;
    }
}

// ---------------------------------------------------------------------------
// Kernel 2: HMMA (mma.sync fp16) GEMM, fp16 in / fp16 out (R12-R14, unchanged)
//   CTA 128x128, BK=64, 512 threads / 16 warps (4Mx4N), warp tile 32x32.
// ---------------------------------------------------------------------------
#define ROW_B   144
#define TILE_B  (128 * ROW_B)
#define STAGE_B (2 * TILE_B)
#define NSTAGES 3
#define GSMEM   (NSTAGES * STAGE_B)
#define KSTAGES 8

__global__ __launch_bounds__(512, 2)
void gemm_hmma_kernel(const __half* __restrict__ A,
                      const __half* __restrict__ B,
                      const float* __restrict__ bias,
                      __half* __restrict__ C) {
    extern __shared__ __align__(128) char smem[];
    const uint32_t sb = smem_u32(smem);
    const int tid = threadIdx.x;
    const int lane = tid & 31;
    const int wid = tid >> 5;
    const int wm = wid & 3;
    const int wn = wid >> 2;

    const size_t mBase = (size_t)(blockIdx.x >> 2) * 128;
    const size_t nBase = (size_t)(blockIdx.x & 3) * 128;

    float acc[2][4][4];
#pragma unroll
    for (int i = 0; i < 2; i++)
#pragma unroll
        for (int j = 0; j < 4; j++)
#pragma unroll
            for (int k = 0; k < 4; k++) acc[i][j][k] = 0.f;

    auto issue = [&](int s) {
        const int koff = s * 64;
        const uint32_t stA = sb + (s % NSTAGES) * STAGE_B;
        const uint32_t stB = stA + TILE_B;
#pragma unroll
        for (int j = 0; j < 2; j++) {
            const int c = tid + j * 512;
            const int row = c >> 3, col = c & 7;
            cp_async16(stA + row * ROW_B + col * 16,
                       A + (mBase + row) * 512 + koff + col * 8);
            cp_async16(stB + row * ROW_B + col * 16,
                       B + (nBase + row) * 512 + koff + col * 8);
        }
        cp_commit();
    };

    issue(0);
    issue(1);

    const int a_lr = lane & 15;
    const int a_kc = lane >> 4;
    const int b_g  = lane >> 3;
    const int b_nr = (b_g >> 1) * 8 + (lane & 7);
    const int b_kc = b_g & 1;

    for (int s = 0; s < KSTAGES; s++) {
        cp_wait1();
        __syncthreads();
        if (s + 2 < KSTAGES) issue(s + 2);
        else cp_commit();

        const uint32_t stA = sb + (s % NSTAGES) * STAGE_B;
        const uint32_t stB = stA + TILE_B;

#pragma unroll
        for (int kk = 0; kk < 4; kk++) {
            uint32_t af[2][4];
#pragma unroll
            for (int mi = 0; mi < 2; mi++) {
                uint32_t addr = stA + (wm * 32 + mi * 16 + a_lr) * ROW_B
                              + kk * 32 + a_kc * 16;
                ldsm_x4(af[mi][0], af[mi][1], af[mi][2], af[mi][3], addr);
            }
#pragma unroll
            for (int nj = 0; nj < 2; nj++) {
                uint32_t b0, b1, b2, b3;
                uint32_t addr = stB + (wn * 32 + nj * 16 + b_nr) * ROW_B
                              + kk * 32 + b_kc * 16;
                ldsm_x4(b0, b1, b2, b3, addr);
                uint32_t bf0[2] = {b0, b1};
                uint32_t bf1[2] = {b2, b3};
#pragma unroll
                for (int mi = 0; mi < 2; mi++) {
                    mma_f16(acc[mi][nj * 2 + 0], af[mi], bf0);
                    mma_f16(acc[mi][nj * 2 + 1], af[mi], bf1);
                }
            }
        }
    }
    cp_wait0();

    const int rr = lane >> 2;
    const int cc = (lane & 3) * 2;
#pragma unroll
    for (int mi = 0; mi < 2; mi++) {
        const size_t row0 = mBase + wm * 32 + mi * 16 + rr;
#pragma unroll
        for (int ns = 0; ns < 4; ns++) {
            const size_t col = nBase + wn * 32 + ns * 8 + cc;
            const float2 bv = *(const float2*)(bias + col);
            __half2 v0 = __floats2half2_rn(acc[mi][ns][0] + bv.x,
                                           acc[mi][ns][1] + bv.y);
            __half2 v1 = __floats2half2_rn(acc[mi][ns][2] + bv.x,
                                           acc[mi][ns][3] + bv.y);
            *(__half2*)(C + row0 * 512 + col) = v0;
            *(__half2*)(C + (row0 + 8) * 512 + col) = v1;
        }
    }
}

// ---------------------------------------------------------------------------
// Kernels 3: IndRNN recurrence, 148-block balanced channel partition.
//   Each block owns an 8-aligned channel range of ~216-232 channels
//   (chStart(b) = (b*BH/148) & ~7), so every SM is active and the busiest
//   SM carries ~228 channels instead of 256. 128 threads x 2 ch/thread,
//   cp.async smem staging (8 stages x 16 timesteps, fixed 512B row stride,
//   predicated chunk issue). Per-channel chains independent; arithmetic
//   identical -> bit-identical results.
// ---------------------------------------------------------------------------
#define RTC   16                      // timesteps per stage
#define RNS   8                       // stages
#define RROWB 512                     // fixed bytes per timestep row in smem
#define RSTG  (RTC * RROWB)           // 8192 bytes per stage
#define RSM   (RNS * RSTG)            // 65536 bytes
#define RGRID 148

__device__ __forceinline__ int rec_ch_start(int b) {
    return (int)(((long long)b * BH) / RGRID) & ~7;
}

__device__ __forceinline__ void rec_issue(uint32_t sbase, int s,
                                          const __half* pre, int chStart,
                                          int nchunk, int tid) {
    const uint32_t st = sbase + (s % RNS) * RSTG;
#pragma unroll
    for (int j = 0; j < 4; j++) {
        const int c = tid + j * 128;
        const int row = c >> 5;          // fixed 32-chunk (512B) row stride
        const int col = c & 31;
        if (col < nchunk)
            cp_async16(st + row * RROWB + col * 16,
                       pre + (size_t)(s * RTC + row) * BH + chStart + col * 8);
    }
    cp_commit();
}

__global__ __launch_bounds__(128)
void rec_h2h_kernel(const __half* __restrict__ pre,
                    __half* __restrict__ out,
                    const float* __restrict__ h_init,
                    const float* __restrict__ u,
                    float* __restrict__ h_final) {
    __shared__ __align__(16) char sbuf[RSM];
    const uint32_t sbase = smem_u32(sbuf);
    const int tid = threadIdx.x;
    const int chStart = rec_ch_start(blockIdx.x);
    const int nch = rec_ch_start(blockIdx.x + 1) - chStart;
    const int nchunk = nch >> 3;
    const int ch0 = chStart + tid * 2;
    const bool act = (tid * 2) < nch;

    const float uu0 = act ? u[ch0 & (H_SZ - 1)] : 0.f;
    const float uu1 = act ? u[(ch0 + 1) & (H_SZ - 1)] : 0.f;
    float h0 = act ? h_init[ch0] : 0.f;
    float h1 = act ? h_init[ch0 + 1] : 0.f;

#pragma unroll
    for (int s = 0; s < RNS - 1; s++)
        rec_issue(sbase, s, pre, chStart, nchunk, tid);

    for (int s = 0; s < T_LEN / RTC; s++) {
        cp_wait6();                    // group s complete (7+s issued, wait<=6)
        __syncthreads();
        const char* hb = sbuf + (s % RNS) * RSTG;
#pragma unroll
        for (int j = 0; j < RTC; j++) {
            __half2 p = *(const __half2*)(hb + j * RROWB + tid * 4);
            h0 = fmaxf(fmaf(uu0, h0, __low2float(p)), 0.f);
            h1 = fmaxf(fmaf(uu1, h1, __high2float(p)), 0.f);
            if (act)
                *(__half2*)(out + (size_t)(s * RTC + j) * BH + ch0) =
                    __floats2half2_rn(h0, h1);
        }
        if (s + RNS - 1 < T_LEN / RTC)
            rec_issue(sbase, s + RNS - 1, pre, chStart, nchunk, tid);
        else
            cp_commit();               // empty group: tail correctness
    }
    if (act) {
        float2 hf; hf.x = h0; hf.y = h1;
        *(float2*)(h_final + ch0) = hf;
    }
}

__global__ __launch_bounds__(128)
void rec_h2f_kernel(const __half* __restrict__ pre,
                    float* __restrict__ out,
                    const float* __restrict__ h_init,
                    const float* __restrict__ u,
                    float* __restrict__ h_final) {
    __shared__ __align__(16) char sbuf[RSM];
    const uint32_t sbase = smem_u32(sbuf);
    const int tid = threadIdx.x;
    const int chStart = rec_ch_start(blockIdx.x);
    const int nch = rec_ch_start(blockIdx.x + 1) - chStart;
    const int nchunk = nch >> 3;
    const int ch0 = chStart + tid * 2;
    const bool act = (tid * 2) < nch;

    const float uu0 = act ? u[ch0 & (H_SZ - 1)] : 0.f;
    const float uu1 = act ? u[(ch0 + 1) & (H_SZ - 1)] : 0.f;
    float h0 = act ? h_init[ch0] : 0.f;
    float h1 = act ? h_init[ch0 + 1] : 0.f;

#pragma unroll
    for (int s = 0; s < RNS - 1; s++)
        rec_issue(sbase, s, pre, chStart, nchunk, tid);

    for (int s = 0; s < T_LEN / RTC; s++) {
        cp_wait6();
        __syncthreads();
        const char* hb = sbuf + (s % RNS) * RSTG;
#pragma unroll
        for (int j = 0; j < RTC; j++) {
            __half2 p = *(const __half2*)(hb + j * RROWB + tid * 4);
            h0 = fmaxf(fmaf(uu0, h0, __low2float(p)), 0.f);
            h1 = fmaxf(fmaf(uu1, h1, __high2float(p)), 0.f);
            if (act) {
                float2 v; v.x = h0; v.y = h1;
                *(float2*)(out + (size_t)(s * RTC + j) * BH + ch0) = v;
            }
        }
        if (s + RNS - 1 < T_LEN / RTC)
            rec_issue(sbase, s + RNS - 1, pre, chStart, nchunk, tid);
        else
            cp_commit();               // empty group: tail correctness
    }
    if (act) {
        float2 hf; hf.x = h0; hf.y = h1;
        *(float2*)(h_final + ch0) = hf;
    }
}

// ---------------------------------------------------------------------------
// Launch
//   inputs: x, hidden, fc_w, fc_b, w0, b0, u0, w1, b1, u1
//   output: [ out1 (T*B*H) | hn (2*B*H) ]
// ---------------------------------------------------------------------------
extern "C" void kernel_launch(void* const* d_in, const int* in_sizes, int n_in,
                              void* d_out, int out_size) {
    const float* x      = (const float*)d_in[0];
    const float* hidden = (const float*)d_in[1];
    const float* fc_w   = (const float*)d_in[2];
    const float* fc_b   = (const float*)d_in[3];
    const float* w0     = (const float*)d_in[4];
    const float* b0     = (const float*)d_in[5];
    const float* u0     = (const float*)d_in[6];
    const float* w1     = (const float*)d_in[7];
    const float* b1     = (const float*)d_in[8];
    const float* u1     = (const float*)d_in[9];
    float* out = (float*)d_out;

    float *bc;
    __half *Wch, *w1h, *xh, *o0h, *pre;
    cudaGetSymbolAddress((void**)&bc,  g_bc);
    cudaGetSymbolAddress((void**)&pre, g_pre);
    cudaGetSymbolAddress((void**)&Wch, g_Wch);
    cudaGetSymbolAddress((void**)&w1h, g_w1h);
    cudaGetSymbolAddress((void**)&xh,  g_xh);
    cudaGetSymbolAddress((void**)&o0h, g_o0h);

    cudaFuncSetAttribute(gemm_hmma_kernel,
                         cudaFuncAttributeMaxDynamicSharedMemorySize, GSMEM);

    // 1) mega-prep: weight fusion + w1 convert + bias + x convert, one launch
    prep_kernel<<<PREP_GRID, 256>>>(w0, fc_w, w1, fc_b, b0, x);

    // 2) pre0 = x @ Wch^T + bc   (fp16 out)
    gemm_hmma_kernel<<<T_LEN * B_SZ / 128 * 4, 512, GSMEM>>>(xh, Wch, bc, pre);

    // 3) layer-0 recurrence -> fp16 out0, h0_final
    rec_h2h_kernel<<<RGRID, 128>>>(pre, o0h, hidden, u0, out + TBH);

    // 4) pre1 = out0 @ w1h^T + b1   (fp16 out)
    gemm_hmma_kernel<<<T_LEN * B_SZ / 128 * 4, 512, GSMEM>>>(o0h, w1h, b1, pre);

    // 5) layer-1 recurrence -> d_out, h1_final
    rec_h2f_kernel<<<RGRID, 128>>>(pre, out, hidden + BH, u1, out + TBH + BH);
}

// round 16
// speedup vs baseline: 1.0056x; 1.0056x over previous
#include <cuda_runtime.h>
#include <cuda_fp16.h>
#include <cstdint>

// Problem constants
#define T_LEN 1024
#define B_SZ  64
#define D_SZ  512
#define H_SZ  512
#define BH    (B_SZ * H_SZ)          // 32768
#define TBH   (T_LEN * BH)           // 33554432

// ---------------------------------------------------------------------------
// Scratch (static device globals; allocation-free per harness rules)
// ---------------------------------------------------------------------------
__device__ float  g_bc[D_SZ];
__device__ __half g_Wch[D_SZ * D_SZ];    // fused fc->layer0 weight, fp16
__device__ __half g_w1h[D_SZ * D_SZ];    // w1, fp16
__device__ __half g_xh[TBH];             // fp16(x)
__device__ __half g_o0h[TBH];            // fp16(out0)
__device__ __half g_pre[TBH];            // fp16 pre-activations (both layers)

// ---------------------------------------------------------------------------
// sm_80-compatible PTX helpers (cp.async / ldmatrix / mma.sync — base sm_103)
// ---------------------------------------------------------------------------
__device__ __forceinline__ uint32_t smem_u32(const void* p) {
    uint32_t a;
    asm("{ .reg .u64 t; cvta.to.shared.u64 t, %1; cvt.u32.u64 %0, t; }"
        : "=r"(a) : "l"(p));
    return a;
}

__device__ __forceinline__ void cp_async16(uint32_t dst, const void* src) {
    asm volatile("cp.async.cg.shared.global [%0], [%1], 16;"
                 :: "r"(dst), "l"(src));
}
__device__ __forceinline__ void cp_commit() {
    asm volatile("cp.async.commit_group;");
}
__device__ __forceinline__ void cp_wait1() {
    asm volatile("cp.async.wait_group 1;");
}
__device__ __forceinline__ void cp_wait10() {
    asm volatile("cp.async.wait_group 10;");
}
__device__ __forceinline__ void cp_wait0() {
    asm volatile("cp.async.wait_group 0;");
}

__device__ __forceinline__ void ldsm_x4(uint32_t& r0, uint32_t& r1,
                                        uint32_t& r2, uint32_t& r3,
                                        uint32_t addr) {
    asm volatile("ldmatrix.sync.aligned.m8n8.x4.shared.b16 {%0,%1,%2,%3}, [%4];"
                 : "=r"(r0), "=r"(r1), "=r"(r2), "=r"(r3) : "r"(addr));
}

__device__ __forceinline__ void mma_f16(float* d, const uint32_t* a,
                                        const uint32_t* b) {
    asm volatile(
        "mma.sync.aligned.m16n8k16.row.col.f32.f16.f16.f32 "
        "{%0,%1,%2,%3}, {%4,%5,%6,%7}, {%8,%9}, {%0,%1,%2,%3};"
        : "+f"(d[0]), "+f"(d[1]), "+f"(d[2]), "+f"(d[3])
        : "r"(a[0]), "r"(a[1]), "r"(a[2]), "r"(a[3]), "r"(b[0]), "r"(b[1]));
}

// ---------------------------------------------------------------------------
// Kernel 1: mega-prep. One launch, grid-partitioned (256 threads each):
//   blocks [0,64):      Wch = fp16(w0 @ fc_w)   (64x64 tiles, compute-bound)
//   blocks [64,320):    w1 -> fp16              (DRAM-bound)
//   blocks [320,322):   bc[h] = w0[h,:]·fc_b + b0[h]
//   blocks [322,33090): x -> fp16               (DRAM-bound, overlaps fuse)
// ---------------------------------------------------------------------------
#define PREP_FUSE_BLKS   64
#define PREP_W1_BLKS     256
#define PREP_BIAS_BLKS   2
#define PREP_X_BLKS      (TBH / 4 / 256)          // 32768
#define PREP_GRID        (PREP_FUSE_BLKS + PREP_W1_BLKS + PREP_BIAS_BLKS + PREP_X_BLKS)

__global__ __launch_bounds__(256)
void prep_kernel(const float* __restrict__ w0,
                 const float* __restrict__ fc_w,
                 const float* __restrict__ w1,
                 const float* __restrict__ fc_b,
                 const float* __restrict__ b0,
                 const float* __restrict__ x) {
    const int bid = blockIdx.x;
    const int tid = threadIdx.x;

    if (bid < PREP_FUSE_BLKS) {
        // ---- weight fusion GEMM: 64x64 tile ----
        __shared__ float As[16][64];   // As[k][m]
        __shared__ float Bs[16][64];   // Bs[k][n]
        const int ty = tid >> 4, tx = tid & 15;
        const int hBase = (bid >> 3) * 64;
        const int eBase = (bid & 7) * 64;

        float acc[4][4];
#pragma unroll
        for (int i = 0; i < 4; i++)
#pragma unroll
            for (int j = 0; j < 4; j++) acc[i][j] = 0.f;

        for (int k0 = 0; k0 < D_SZ; k0 += 16) {
            {
                int id = tid * 4;
                int row = id >> 4, col = id & 15;
                float4 v = *(const float4*)(w0 + (hBase + row) * D_SZ + k0 + col);
                As[col + 0][row] = v.x;
                As[col + 1][row] = v.y;
                As[col + 2][row] = v.z;
                As[col + 3][row] = v.w;
            }
            {
                int id = tid * 4;
                int r = id >> 6, c = id & 63;
                float4 v = *(const float4*)(fc_w + (k0 + r) * D_SZ + eBase + c);
                Bs[r][c + 0] = v.x;
                Bs[r][c + 1] = v.y;
                Bs[r][c + 2] = v.z;
                Bs[r][c + 3] = v.w;
            }
            __syncthreads();
#pragma unroll
            for (int k = 0; k < 16; k++) {
                float ra[4], rb[4];
#pragma unroll
                for (int i = 0; i < 4; i++) ra[i] = As[k][ty * 4 + i];
#pragma unroll
                for (int j = 0; j < 4; j++) rb[j] = Bs[k][tx * 4 + j];
#pragma unroll
                for (int i = 0; i < 4; i++)
#pragma unroll
                    for (int j = 0; j < 4; j++)
                        acc[i][j] = fmaf(ra[i], rb[j], acc[i][j]);
            }
            __syncthreads();
        }
#pragma unroll
        for (int i = 0; i < 4; i++)
#pragma unroll
            for (int j = 0; j < 4; j++)
                g_Wch[(hBase + ty * 4 + i) * D_SZ + eBase + tx * 4 + j] =
                    __float2half_rn(acc[i][j]);
    } else if (bid < PREP_FUSE_BLKS + PREP_W1_BLKS) {
        // ---- w1 fp32 -> fp16 ----
        int i = (bid - PREP_FUSE_BLKS) * 256 + tid;      // n4 = 65536
        float4 v = ((const float4*)w1)[i];
        __half2 a; a.x = __float2half_rn(v.x); a.y = __float2half_rn(v.y);
        __half2 b; b.x = __float2half_rn(v.z); b.y = __float2half_rn(v.w);
        ((__half2*)g_w1h)[i * 2 + 0] = a;
        ((__half2*)g_w1h)[i * 2 + 1] = b;
    } else if (bid < PREP_FUSE_BLKS + PREP_W1_BLKS + PREP_BIAS_BLKS) {
        // ---- fused bias ----
        int h = (bid - PREP_FUSE_BLKS - PREP_W1_BLKS) * 256 + tid;
        float acc = b0[h];
        const float* row = w0 + h * D_SZ;
#pragma unroll 8
        for (int d = 0; d < D_SZ; d++)
            acc = fmaf(row[d], fc_b[d], acc);
        g_bc[h] = acc;
    } else {
        // ---- x fp32 -> fp16 ----
        int i = (bid - PREP_FUSE_BLKS - PREP_W1_BLKS - PREP_BIAS_BLKS) * 256 + tid;
        float4 v = ((const float4*)x)[i];
        __half2 a; a.x = __float2half_rn(v.x); a.y = __float2half_rn(v.y);
        __half2 b; b.x = __float2half_rn(v.z); b.y = __float2half_rn(v.w);
        ((__half2*)g_xh)[i * 2 + 0] = a;
        ((__half2*)g_xh)[i * 2 + 1] = b;
    }
}

// ---------------------------------------------------------------------------
// Kernel 2: HMMA (mma.sync fp16) GEMM, fp16 in / fp16 out (R12-R14, unchanged)
//   CTA 128x128, BK=64, 512 threads / 16 warps (4Mx4N), warp tile 32x32.
// ---------------------------------------------------------------------------
#define ROW_B   144
#define TILE_B  (128 * ROW_B)
#define STAGE_B (2 * TILE_B)
#define NSTAGES 3
#define GSMEM   (NSTAGES * STAGE_B)
#define KSTAGES 8

__global__ __launch_bounds__(512, 2)
void gemm_hmma_kernel(const __half* __restrict__ A,
                      const __half* __restrict__ B,
                      const float* __restrict__ bias,
                      __half* __restrict__ C) {
    extern __shared__ __align__(128) char smem[];
    const uint32_t sb = smem_u32(smem);
    const int tid = threadIdx.x;
    const int lane = tid & 31;
    const int wid = tid >> 5;
    const int wm = wid & 3;
    const int wn = wid >> 2;

    const size_t mBase = (size_t)(blockIdx.x >> 2) * 128;
    const size_t nBase = (size_t)(blockIdx.x & 3) * 128;

    float acc[2][4][4];
#pragma unroll
    for (int i = 0; i < 2; i++)
#pragma unroll
        for (int j = 0; j < 4; j++)
#pragma unroll
            for (int k = 0; k < 4; k++) acc[i][j][k] = 0.f;

    auto issue = [&](int s) {
        const int koff = s * 64;
        const uint32_t stA = sb + (s % NSTAGES) * STAGE_B;
        const uint32_t stB = stA + TILE_B;
#pragma unroll
        for (int j = 0; j < 2; j++) {
            const int c = tid + j * 512;
            const int row = c >> 3, col = c & 7;
            cp_async16(stA + row * ROW_B + col * 16,
                       A + (mBase + row) * 512 + koff + col * 8);
            cp_async16(stB + row * ROW_B + col * 16,
                       B + (nBase + row) * 512 + koff + col * 8);
        }
        cp_commit();
    };

    issue(0);
    issue(1);

    const int a_lr = lane & 15;
    const int a_kc = lane >> 4;
    const int b_g  = lane >> 3;
    const int b_nr = (b_g >> 1) * 8 + (lane & 7);
    const int b_kc = b_g & 1;

    for (int s = 0; s < KSTAGES; s++) {
        cp_wait1();
        __syncthreads();
        if (s + 2 < KSTAGES) issue(s + 2);
        else cp_commit();

        const uint32_t stA = sb + (s % NSTAGES) * STAGE_B;
        const uint32_t stB = stA + TILE_B;

#pragma unroll
        for (int kk = 0; kk < 4; kk++) {
            uint32_t af[2][4];
#pragma unroll
            for (int mi = 0; mi < 2; mi++) {
                uint32_t addr = stA + (wm * 32 + mi * 16 + a_lr) * ROW_B
                              + kk * 32 + a_kc * 16;
                ldsm_x4(af[mi][0], af[mi][1], af[mi][2], af[mi][3], addr);
            }
#pragma unroll
            for (int nj = 0; nj < 2; nj++) {
                uint32_t b0, b1, b2, b3;
                uint32_t addr = stB + (wn * 32 + nj * 16 + b_nr) * ROW_B
                              + kk * 32 + b_kc * 16;
                ldsm_x4(b0, b1, b2, b3, addr);
                uint32_t bf0[2] = {b0, b1};
                uint32_t bf1[2] = {b2, b3};
#pragma unroll
                for (int mi = 0; mi < 2; mi++) {
                    mma_f16(acc[mi][nj * 2 + 0], af[mi], bf0);
                    mma_f16(acc[mi][nj * 2 + 1], af[mi], bf1);
                }
            }
        }
    }
    cp_wait0();

    const int rr = lane >> 2;
    const int cc = (lane & 3) * 2;
#pragma unroll
    for (int mi = 0; mi < 2; mi++) {
        const size_t row0 = mBase + wm * 32 + mi * 16 + rr;
#pragma unroll
        for (int ns = 0; ns < 4; ns++) {
            const size_t col = nBase + wn * 32 + ns * 8 + cc;
            const float2 bv = *(const float2*)(bias + col);
            __half2 v0 = __floats2half2_rn(acc[mi][ns][0] + bv.x,
                                           acc[mi][ns][1] + bv.y);
            __half2 v1 = __floats2half2_rn(acc[mi][ns][2] + bv.x,
                                           acc[mi][ns][3] + bv.y);
            *(__half2*)(C + row0 * 512 + col) = v0;
            *(__half2*)(C + (row0 + 8) * 512 + col) = v1;
        }
    }
}

// ---------------------------------------------------------------------------
// Kernels 3: IndRNN recurrence, 2 channels/thread, vectorized I/O (R14 config
//   with deeper pipeline). 128 threads x 2 ch = 256 ch/block, 128 blocks.
//   Dynamic smem: 12 stages x 16 timesteps x 512B = 96KB; wait_group 10 keeps
//   11 stages (88KB) in flight. Empty commits keep tail arithmetic exact.
// ---------------------------------------------------------------------------
#define RTC  16                       // timesteps per stage
#define RNS  12                       // stages (deeper pipeline)
#define RCH  256                      // channels per block
#define RROW (RCH * 2)                // 512 bytes per timestep row
#define RSTG (RTC * RROW)             // 8192 bytes per stage
#define RSM  (RNS * RSTG)             // 98304 bytes (dynamic)

__device__ __forceinline__ void rec_issue(uint32_t sbase, int s,
                                          const __half* pre, int chBase,
                                          int tid) {
    const uint32_t st = sbase + (s % RNS) * RSTG;
#pragma unroll
    for (int j = 0; j < 4; j++) {
        const int c = tid + j * 128;     // 512 chunks: 16 rows x 32 chunks
        const int row = c >> 5, col = c & 31;
        cp_async16(st + row * RROW + col * 16,
                   pre + (size_t)(s * RTC + row) * BH + chBase + col * 8);
    }
    cp_commit();
}

__global__ __launch_bounds__(128)
void rec_h2h_kernel(const __half* __restrict__ pre,
                    __half* __restrict__ out,
                    const float* __restrict__ h_init,
                    const float* __restrict__ u,
                    float* __restrict__ h_final) {
    extern __shared__ __align__(16) char sbuf[];
    const uint32_t sbase = smem_u32(sbuf);
    const int tid = threadIdx.x;
    const int chBase = blockIdx.x * RCH;
    const int ch0 = chBase + tid * 2;
    const float uu0 = u[ch0 & (H_SZ - 1)];
    const float uu1 = u[(ch0 + 1) & (H_SZ - 1)];
    float h0 = h_init[ch0], h1 = h_init[ch0 + 1];

#pragma unroll
    for (int s = 0; s < RNS - 1; s++) rec_issue(sbase, s, pre, chBase, tid);

    for (int s = 0; s < T_LEN / RTC; s++) {
        cp_wait10();                   // group s complete (11+s issued, wait<=10)
        __syncthreads();
        const char* hb = sbuf + (s % RNS) * RSTG;
#pragma unroll
        for (int j = 0; j < RTC; j++) {
            __half2 p = ((const __half2*)(hb + j * RROW))[tid];
            h0 = fmaxf(fmaf(uu0, h0, __low2float(p)), 0.f);
            h1 = fmaxf(fmaf(uu1, h1, __high2float(p)), 0.f);
            *(__half2*)(out + (size_t)(s * RTC + j) * BH + ch0) =
                __floats2half2_rn(h0, h1);
        }
        if (s + RNS - 1 < T_LEN / RTC)
            rec_issue(sbase, s + RNS - 1, pre, chBase, tid);
        else
            cp_commit();               // empty group: tail correctness
    }
    float2 hf; hf.x = h0; hf.y = h1;
    *(float2*)(h_final + ch0) = hf;
}

__global__ __launch_bounds__(128)
void rec_h2f_kernel(const __half* __restrict__ pre,
                    float* __restrict__ out,
                    const float* __restrict__ h_init,
                    const float* __restrict__ u,
                    float* __restrict__ h_final) {
    extern __shared__ __align__(16) char sbuf[];
    const uint32_t sbase = smem_u32(sbuf);
    const int tid = threadIdx.x;
    const int chBase = blockIdx.x * RCH;
    const int ch0 = chBase + tid * 2;
    const float uu0 = u[ch0 & (H_SZ - 1)];
    const float uu1 = u[(ch0 + 1) & (H_SZ - 1)];
    float h0 = h_init[ch0], h1 = h_init[ch0 + 1];

#pragma unroll
    for (int s = 0; s < RNS - 1; s++) rec_issue(sbase, s, pre, chBase, tid);

    for (int s = 0; s < T_LEN / RTC; s++) {
        cp_wait10();
        __syncthreads();
        const char* hb = sbuf + (s % RNS) * RSTG;
#pragma unroll
        for (int j = 0; j < RTC; j++) {
            __half2 p = ((const __half2*)(hb + j * RROW))[tid];
            h0 = fmaxf(fmaf(uu0, h0, __low2float(p)), 0.f);
            h1 = fmaxf(fmaf(uu1, h1, __high2float(p)), 0.f);
            float2 v; v.x = h0; v.y = h1;
            *(float2*)(out + (size_t)(s * RTC + j) * BH + ch0) = v;
        }
        if (s + RNS - 1 < T_LEN / RTC)
            rec_issue(sbase, s + RNS - 1, pre, chBase, tid);
        else
            cp_commit();               // empty group: tail correctness
    }
    float2 hf; hf.x = h0; hf.y = h1;
    *(float2*)(h_final + ch0) = hf;
}

// ---------------------------------------------------------------------------
// Launch
//   inputs: x, hidden, fc_w, fc_b, w0, b0, u0, w1, b1, u1
//   output: [ out1 (T*B*H) | hn (2*B*H) ]
// ---------------------------------------------------------------------------
extern "C" void kernel_launch(void* const* d_in, const int* in_sizes, int n_in,
                              void* d_out, int out_size) {
    const float* x      = (const float*)d_in[0];
    const float* hidden = (const float*)d_in[1];
    const float* fc_w   = (const float*)d_in[2];
    const float* fc_b   = (const float*)d_in[3];
    const float* w0     = (const float*)d_in[4];
    const float* b0     = (const float*)d_in[5];
    const float* u0     = (const float*)d_in[6];
    const float* w1     = (const float*)d_in[7];
    const float* b1     = (const float*)d_in[8];
    const float* u1     = (const float*)d_in[9];
    float* out = (float*)d_out;

    float *bc;
    __half *Wch, *w1h, *xh, *o0h, *pre;
    cudaGetSymbolAddress((void**)&bc,  g_bc);
    cudaGetSymbolAddress((void**)&pre, g_pre);
    cudaGetSymbolAddress((void**)&Wch, g_Wch);
    cudaGetSymbolAddress((void**)&w1h, g_w1h);
    cudaGetSymbolAddress((void**)&xh,  g_xh);
    cudaGetSymbolAddress((void**)&o0h, g_o0h);

    cudaFuncSetAttribute(gemm_hmma_kernel,
                         cudaFuncAttributeMaxDynamicSharedMemorySize, GSMEM);
    cudaFuncSetAttribute(rec_h2h_kernel,
                         cudaFuncAttributeMaxDynamicSharedMemorySize, RSM);
    cudaFuncSetAttribute(rec_h2f_kernel,
                         cudaFuncAttributeMaxDynamicSharedMemorySize, RSM);

    // 1) mega-prep: weight fusion + w1 convert + bias + x convert, one launch
    prep_kernel<<<PREP_GRID, 256>>>(w0, fc_w, w1, fc_b, b0, x);

    // 2) pre0 = x @ Wch^T + bc   (fp16 out)
    gemm_hmma_kernel<<<T_LEN * B_SZ / 128 * 4, 512, GSMEM>>>(xh, Wch, bc, pre);

    // 3) layer-0 recurrence -> fp16 out0, h0_final
    rec_h2h_kernel<<<BH / RCH, 128, RSM>>>(pre, o0h, hidden, u0, out + TBH);

    // 4) pre1 = out0 @ w1h^T + b1   (fp16 out)
    gemm_hmma_kernel<<<T_LEN * B_SZ / 128 * 4, 512, GSMEM>>>(o0h, w1h, b1, pre);

    // 5) layer-1 recurrence -> d_out, h1_final
    rec_h2f_kernel<<<BH / RCH, 128, RSM>>>(pre, out, hidden + BH, u1, out + TBH + BH);
}

// round 17
// speedup vs baseline: 1.0243x; 1.0186x over previous
#include <cuda_runtime.h>
#include <cuda_fp16.h>
#include <cstdint>

// Problem constants
#define T_LEN 1024
#define B_SZ  64
#define D_SZ  512
#define H_SZ  512
#define BH    (B_SZ * H_SZ)          // 32768
#define TBH   (T_LEN * BH)           // 33554432

// ---------------------------------------------------------------------------
// Scratch (static device globals; allocation-free per harness rules)
// ---------------------------------------------------------------------------
__device__ float  g_bc[D_SZ];
__device__ __half g_Wch[D_SZ * D_SZ];    // fused fc->layer0 weight, fp16
__device__ __half g_w1h[D_SZ * D_SZ];    // w1, fp16
__device__ __half g_xh[TBH];             // fp16(x)
__device__ __half g_o0h[TBH];            // fp16(out0)
__device__ __half g_pre[TBH];            // fp16 pre-activations (both layers)

// ---------------------------------------------------------------------------
// sm_80-compatible PTX helpers (cp.async / ldmatrix / mma.sync — base sm_103)
// ---------------------------------------------------------------------------
__device__ __forceinline__ uint32_t smem_u32(const void* p) {
    uint32_t a;
    asm("{ .reg .u64 t; cvta.to.shared.u64 t, %1; cvt.u32.u64 %0, t; }"
        : "=r"(a) : "l"(p));
    return a;
}

__device__ __forceinline__ void cp_async16(uint32_t dst, const void* src) {
    asm volatile("cp.async.cg.shared.global [%0], [%1], 16;"
                 :: "r"(dst), "l"(src));
}
__device__ __forceinline__ void cp_commit() {
    asm volatile("cp.async.commit_group;");
}
__device__ __forceinline__ void cp_wait1() {
    asm volatile("cp.async.wait_group 1;");
}
__device__ __forceinline__ void cp_wait6() {
    asm volatile("cp.async.wait_group 6;");
}
__device__ __forceinline__ void cp_wait0() {
    asm volatile("cp.async.wait_group 0;");
}

__device__ __forceinline__ void ldsm_x4(uint32_t& r0, uint32_t& r1,
                                        uint32_t& r2, uint32_t& r3,
                                        uint32_t addr) {
    asm volatile("ldmatrix.sync.aligned.m8n8.x4.shared.b16 {%0,%1,%2,%3}, [%4];"
                 : "=r"(r0), "=r"(r1), "=r"(r2), "=r"(r3) : "r"(addr));
}

__device__ __forceinline__ void mma_f16(float* d, const uint32_t* a,
                                        const uint32_t* b) {
    asm volatile(
        "mma.sync.aligned.m16n8k16.row.col.f32.f16.f16.f32 "
        "{%0,%1,%2,%3}, {%4,%5,%6,%7}, {%8,%9}, {%0,%1,%2,%3};"
        : "+f"(d[0]), "+f"(d[1]), "+f"(d[2]), "+f"(d[3])
        : "r"(a[0]), "r"(a[1]), "r"(a[2]), "r"(a[3]), "r"(b[0]), "r"(b[1]));
}

// ---------------------------------------------------------------------------
// Kernel 1: mega-prep. One launch, grid-partitioned (256 threads each):
//   blocks [0,64):      Wch = fp16(w0 @ fc_w)   (64x64 tiles, compute-bound)
//   blocks [64,128):    w1 -> fp16              (grid-stride x4, MLP=4)
//   blocks [128,130):   bc[h] = w0[h,:]·fc_b + b0[h]
//   blocks [130,8322):  x -> fp16               (grid-stride x4, MLP=4)
// All parts element-independent; results bit-identical to separate kernels.
// ---------------------------------------------------------------------------
#define PREP_FUSE_BLKS   64
#define PREP_W1_BLKS     64                       // 65536 f4 / (256 thr * 4)
#define PREP_BIAS_BLKS   2
#define PREP_X_BLKS      (TBH / 4 / 256 / 4)      // 8192
#define PREP_GRID        (PREP_FUSE_BLKS + PREP_W1_BLKS + PREP_BIAS_BLKS + PREP_X_BLKS)

__device__ __forceinline__ void cvt4_f32_f16(const float* __restrict__ src,
                                             __half* __restrict__ dst,
                                             int base) {
    // 4 independent float4 loads in flight, then 4 vectorized fp16 stores
    float4 v[4];
#pragma unroll
    for (int j = 0; j < 4; j++)
        v[j] = ((const float4*)src)[base + j * 256];
#pragma unroll
    for (int j = 0; j < 4; j++) {
        int i = base + j * 256;
        __half2 a; a.x = __float2half_rn(v[j].x); a.y = __float2half_rn(v[j].y);
        __half2 b; b.x = __float2half_rn(v[j].z); b.y = __float2half_rn(v[j].w);
        ((__half2*)dst)[i * 2 + 0] = a;
        ((__half2*)dst)[i * 2 + 1] = b;
    }
}

__global__ __launch_bounds__(256)
void prep_kernel(const float* __restrict__ w0,
                 const float* __restrict__ fc_w,
                 const float* __restrict__ w1,
                 const float* __restrict__ fc_b,
                 const float* __restrict__ b0,
                 const float* __restrict__ x) {
    const int bid = blockIdx.x;
    const int tid = threadIdx.x;

    if (bid < PREP_FUSE_BLKS) {
        // ---- weight fusion GEMM: 64x64 tile ----
        __shared__ float As[16][64];   // As[k][m]
        __shared__ float Bs[16][64];   // Bs[k][n]
        const int ty = tid >> 4, tx = tid & 15;
        const int hBase = (bid >> 3) * 64;
        const int eBase = (bid & 7) * 64;

        float acc[4][4];
#pragma unroll
        for (int i = 0; i < 4; i++)
#pragma unroll
            for (int j = 0; j < 4; j++) acc[i][j] = 0.f;

        for (int k0 = 0; k0 < D_SZ; k0 += 16) {
            {
                int id = tid * 4;
                int row = id >> 4, col = id & 15;
                float4 v = *(const float4*)(w0 + (hBase + row) * D_SZ + k0 + col);
                As[col + 0][row] = v.x;
                As[col + 1][row] = v.y;
                As[col + 2][row] = v.z;
                As[col + 3][row] = v.w;
            }
            {
                int id = tid * 4;
                int r = id >> 6, c = id & 63;
                float4 v = *(const float4*)(fc_w + (k0 + r) * D_SZ + eBase + c);
                Bs[r][c + 0] = v.x;
                Bs[r][c + 1] = v.y;
                Bs[r][c + 2] = v.z;
                Bs[r][c + 3] = v.w;
            }
            __syncthreads();
#pragma unroll
            for (int k = 0; k < 16; k++) {
                float ra[4], rb[4];
#pragma unroll
                for (int i = 0; i < 4; i++) ra[i] = As[k][ty * 4 + i];
#pragma unroll
                for (int j = 0; j < 4; j++) rb[j] = Bs[k][tx * 4 + j];
#pragma unroll
                for (int i = 0; i < 4; i++)
#pragma unroll
                    for (int j = 0; j < 4; j++)
                        acc[i][j] = fmaf(ra[i], rb[j], acc[i][j]);
            }
            __syncthreads();
        }
#pragma unroll
        for (int i = 0; i < 4; i++)
#pragma unroll
            for (int j = 0; j < 4; j++)
                g_Wch[(hBase + ty * 4 + i) * D_SZ + eBase + tx * 4 + j] =
                    __float2half_rn(acc[i][j]);
    } else if (bid < PREP_FUSE_BLKS + PREP_W1_BLKS) {
        // ---- w1 fp32 -> fp16, 4 float4 per thread ----
        int base = (bid - PREP_FUSE_BLKS) * 1024 + tid;
        cvt4_f32_f16(w1, g_w1h, base);
    } else if (bid < PREP_FUSE_BLKS + PREP_W1_BLKS + PREP_BIAS_BLKS) {
        // ---- fused bias ----
        int h = (bid - PREP_FUSE_BLKS - PREP_W1_BLKS) * 256 + tid;
        float acc = b0[h];
        const float* row = w0 + h * D_SZ;
#pragma unroll 8
        for (int d = 0; d < D_SZ; d++)
            acc = fmaf(row[d], fc_b[d], acc);
        g_bc[h] = acc;
    } else {
        // ---- x fp32 -> fp16, 4 float4 per thread ----
        int base = (bid - PREP_FUSE_BLKS - PREP_W1_BLKS - PREP_BIAS_BLKS) * 1024 + tid;
        cvt4_f32_f16(x, g_xh, base);
    }
}

// ---------------------------------------------------------------------------
// Kernel 2: HMMA (mma.sync fp16) GEMM, fp16 in / fp16 out (R12-R14, unchanged)
//   CTA 128x128, BK=64, 512 threads / 16 warps (4Mx4N), warp tile 32x32.
// ---------------------------------------------------------------------------
#define ROW_B   144
#define TILE_B  (128 * ROW_B)
#define STAGE_B (2 * TILE_B)
#define NSTAGES 3
#define GSMEM   (NSTAGES * STAGE_B)
#define KSTAGES 8

__global__ __launch_bounds__(512, 2)
void gemm_hmma_kernel(const __half* __restrict__ A,
                      const __half* __restrict__ B,
                      const float* __restrict__ bias,
                      __half* __restrict__ C) {
    extern __shared__ __align__(128) char smem[];
    const uint32_t sb = smem_u32(smem);
    const int tid = threadIdx.x;
    const int lane = tid & 31;
    const int wid = tid >> 5;
    const int wm = wid & 3;
    const int wn = wid >> 2;

    const size_t mBase = (size_t)(blockIdx.x >> 2) * 128;
    const size_t nBase = (size_t)(blockIdx.x & 3) * 128;

    float acc[2][4][4];
#pragma unroll
    for (int i = 0; i < 2; i++)
#pragma unroll
        for (int j = 0; j < 4; j++)
#pragma unroll
            for (int k = 0; k < 4; k++) acc[i][j][k] = 0.f;

    auto issue = [&](int s) {
        const int koff = s * 64;
        const uint32_t stA = sb + (s % NSTAGES) * STAGE_B;
        const uint32_t stB = stA + TILE_B;
#pragma unroll
        for (int j = 0; j < 2; j++) {
            const int c = tid + j * 512;
            const int row = c >> 3, col = c & 7;
            cp_async16(stA + row * ROW_B + col * 16,
                       A + (mBase + row) * 512 + koff + col * 8);
            cp_async16(stB + row * ROW_B + col * 16,
                       B + (nBase + row) * 512 + koff + col * 8);
        }
        cp_commit();
    };

    issue(0);
    issue(1);

    const int a_lr = lane & 15;
    const int a_kc = lane >> 4;
    const int b_g  = lane >> 3;
    const int b_nr = (b_g >> 1) * 8 + (lane & 7);
    const int b_kc = b_g & 1;

    for (int s = 0; s < KSTAGES; s++) {
        cp_wait1();
        __syncthreads();
        if (s + 2 < KSTAGES) issue(s + 2);
        else cp_commit();

        const uint32_t stA = sb + (s % NSTAGES) * STAGE_B;
        const uint32_t stB = stA + TILE_B;

#pragma unroll
        for (int kk = 0; kk < 4; kk++) {
            uint32_t af[2][4];
#pragma unroll
            for (int mi = 0; mi < 2; mi++) {
                uint32_t addr = stA + (wm * 32 + mi * 16 + a_lr) * ROW_B
                              + kk * 32 + a_kc * 16;
                ldsm_x4(af[mi][0], af[mi][1], af[mi][2], af[mi][3], addr);
            }
#pragma unroll
            for (int nj = 0; nj < 2; nj++) {
                uint32_t b0, b1, b2, b3;
                uint32_t addr = stB + (wn * 32 + nj * 16 + b_nr) * ROW_B
                              + kk * 32 + b_kc * 16;
                ldsm_x4(b0, b1, b2, b3, addr);
                uint32_t bf0[2] = {b0, b1};
                uint32_t bf1[2] = {b2, b3};
#pragma unroll
                for (int mi = 0; mi < 2; mi++) {
                    mma_f16(acc[mi][nj * 2 + 0], af[mi], bf0);
                    mma_f16(acc[mi][nj * 2 + 1], af[mi], bf1);
                }
            }
        }
    }
    cp_wait0();

    const int rr = lane >> 2;
    const int cc = (lane & 3) * 2;
#pragma unroll
    for (int mi = 0; mi < 2; mi++) {
        const size_t row0 = mBase + wm * 32 + mi * 16 + rr;
#pragma unroll
        for (int ns = 0; ns < 4; ns++) {
            const size_t col = nBase + wn * 32 + ns * 8 + cc;
            const float2 bv = *(const float2*)(bias + col);
            __half2 v0 = __floats2half2_rn(acc[mi][ns][0] + bv.x,
                                           acc[mi][ns][1] + bv.y);
            __half2 v1 = __floats2half2_rn(acc[mi][ns][2] + bv.x,
                                           acc[mi][ns][3] + bv.y);
            *(__half2*)(C + row0 * 512 + col) = v0;
            *(__half2*)(C + (row0 + 8) * 512 + col) = v1;
        }
    }
}

// ---------------------------------------------------------------------------
// Kernels 3: IndRNN recurrence, 2 channels/thread, vectorized I/O (R14 exact).
//   128 threads x 2 ch = 256 ch/block, 128 blocks (single wave).
//   cp.async smem staging: 8 stages x 16 timesteps (8KB/stage, 64KB static).
//   Empty commits on the tail keep wait_group 6 arithmetic exact.
// ---------------------------------------------------------------------------
#define RTC  16                       // timesteps per stage
#define RNS  8                        // stages
#define RCH  256                      // channels per block
#define RROW (RCH * 2)                // 512 bytes per timestep row
#define RSTG (RTC * RROW)             // 8192 bytes per stage
#define RSM  (RNS * RSTG)             // 65536 bytes

__device__ __forceinline__ void rec_issue(uint32_t sbase, int s,
                                          const __half* pre, int chBase,
                                          int tid) {
    const uint32_t st = sbase + (s % RNS) * RSTG;
#pragma unroll
    for (int j = 0; j < 4; j++) {
        const int c = tid + j * 128;     // 512 chunks: 16 rows x 32 chunks
        const int row = c >> 5, col = c & 31;
        cp_async16(st + row * RROW + col * 16,
                   pre + (size_t)(s * RTC + row) * BH + chBase + col * 8);
    }
    cp_commit();
}

__global__ __launch_bounds__(128)
void rec_h2h_kernel(const __half* __restrict__ pre,
                    __half* __restrict__ out,
                    const float* __restrict__ h_init,
                    const float* __restrict__ u,
                    float* __restrict__ h_final) {
    __shared__ __align__(16) char sbuf[RSM];
    const uint32_t sbase = smem_u32(sbuf);
    const int tid = threadIdx.x;
    const int chBase = blockIdx.x * RCH;
    const int ch0 = chBase + tid * 2;
    const float uu0 = u[ch0 & (H_SZ - 1)];
    const float uu1 = u[(ch0 + 1) & (H_SZ - 1)];
    float h0 = h_init[ch0], h1 = h_init[ch0 + 1];

#pragma unroll
    for (int s = 0; s < RNS - 1; s++) rec_issue(sbase, s, pre, chBase, tid);

    for (int s = 0; s < T_LEN / RTC; s++) {
        cp_wait6();                    // group s complete (7+s issued, wait<=6)
        __syncthreads();
        const char* hb = sbuf + (s % RNS) * RSTG;
#pragma unroll
        for (int j = 0; j < RTC; j++) {
            __half2 p = ((const __half2*)(hb + j * RROW))[tid];
            h0 = fmaxf(fmaf(uu0, h0, __low2float(p)), 0.f);
            h1 = fmaxf(fmaf(uu1, h1, __high2float(p)), 0.f);
            *(__half2*)(out + (size_t)(s * RTC + j) * BH + ch0) =
                __floats2half2_rn(h0, h1);
        }
        if (s + RNS - 1 < T_LEN / RTC)
            rec_issue(sbase, s + RNS - 1, pre, chBase, tid);
        else
            cp_commit();               // empty group: tail correctness
    }
    float2 hf; hf.x = h0; hf.y = h1;
    *(float2*)(h_final + ch0) = hf;
}

__global__ __launch_bounds__(128)
void rec_h2f_kernel(const __half* __restrict__ pre,
                    float* __restrict__ out,
                    const float* __restrict__ h_init,
                    const float* __restrict__ u,
                    float* __restrict__ h_final) {
    __shared__ __align__(16) char sbuf[RSM];
    const uint32_t sbase = smem_u32(sbuf);
    const int tid = threadIdx.x;
    const int chBase = blockIdx.x * RCH;
    const int ch0 = chBase + tid * 2;
    const float uu0 = u[ch0 & (H_SZ - 1)];
    const float uu1 = u[(ch0 + 1) & (H_SZ - 1)];
    float h0 = h_init[ch0], h1 = h_init[ch0 + 1];

#pragma unroll
    for (int s = 0; s < RNS - 1; s++) rec_issue(sbase, s, pre, chBase, tid);

    for (int s = 0; s < T_LEN / RTC; s++) {
        cp_wait6();
        __syncthreads();
        const char* hb = sbuf + (s % RNS) * RSTG;
#pragma unroll
        for (int j = 0; j < RTC; j++) {
            __half2 p = ((const __half2*)(hb + j * RROW))[tid];
            h0 = fmaxf(fmaf(uu0, h0, __low2float(p)), 0.f);
            h1 = fmaxf(fmaf(uu1, h1, __high2float(p)), 0.f);
            float2 v; v.x = h0; v.y = h1;
            *(float2*)(out + (size_t)(s * RTC + j) * BH + ch0) = v;
        }
        if (s + RNS - 1 < T_LEN / RTC)
            rec_issue(sbase, s + RNS - 1, pre, chBase, tid);
        else
            cp_commit();               // empty group: tail correctness
    }
    float2 hf; hf.x = h0; hf.y = h1;
    *(float2*)(h_final + ch0) = hf;
}

// ---------------------------------------------------------------------------
// Launch
//   inputs: x, hidden, fc_w, fc_b, w0, b0, u0, w1, b1, u1
//   output: [ out1 (T*B*H) | hn (2*B*H) ]
// ---------------------------------------------------------------------------
extern "C" void kernel_launch(void* const* d_in, const int* in_sizes, int n_in,
                              void* d_out, int out_size) {
    const float* x      = (const float*)d_in[0];
    const float* hidden = (const float*)d_in[1];
    const float* fc_w   = (const float*)d_in[2];
    const float* fc_b   = (const float*)d_in[3];
    const float* w0     = (const float*)d_in[4];
    const float* b0     = (const float*)d_in[5];
    const float* u0     = (const float*)d_in[6];
    const float* w1     = (const float*)d_in[7];
    const float* b1     = (const float*)d_in[8];
    const float* u1     = (const float*)d_in[9];
    float* out = (float*)d_out;

    float *bc;
    __half *Wch, *w1h, *xh, *o0h, *pre;
    cudaGetSymbolAddress((void**)&bc,  g_bc);
    cudaGetSymbolAddress((void**)&pre, g_pre);
    cudaGetSymbolAddress((void**)&Wch, g_Wch);
    cudaGetSymbolAddress((void**)&w1h, g_w1h);
    cudaGetSymbolAddress((void**)&xh,  g_xh);
    cudaGetSymbolAddress((void**)&o0h, g_o0h);

    cudaFuncSetAttribute(gemm_hmma_kernel,
                         cudaFuncAttributeMaxDynamicSharedMemorySize, GSMEM);

    // 1) mega-prep: weight fusion + w1 convert + bias + x convert, one launch
    prep_kernel<<<PREP_GRID, 256>>>(w0, fc_w, w1, fc_b, b0, x);

    // 2) pre0 = x @ Wch^T + bc   (fp16 out)
    gemm_hmma_kernel<<<T_LEN * B_SZ / 128 * 4, 512, GSMEM>>>(xh, Wch, bc, pre);

    // 3) layer-0 recurrence -> fp16 out0, h0_final
    rec_h2h_kernel<<<BH / RCH, 128>>>(pre, o0h, hidden, u0, out + TBH);

    // 4) pre1 = out0 @ w1h^T + b1   (fp16 out)
    gemm_hmma_kernel<<<T_LEN * B_SZ / 128 * 4, 512, GSMEM>>>(o0h, w1h, b1, pre);

    // 5) layer-1 recurrence -> d_out, h1_final
    rec_h2f_kernel<<<BH / RCH, 128>>>(pre, out, hidden + BH, u1, out + TBH + BH);
}